// round 10
// baseline (speedup 1.0000x reference)
#include <cuda_runtime.h>
#include <cuda_bf16.h>
#include <cstdint>

// Segment-mean readout:
//   out[g, :] = mean(atom_hiddens[start_g : start_g+size_g, :])   (0 if size_g == 0)
// atom_hiddens: [N_ATOMS, D] float32       (1M x 300)
// a_scope:      [N_GRAPHS, 2] int32        (start, size)
//
// HBM/LTS-roofline streaming: 1.2 GB read + 60 MB write, zero reuse.
// Converged config: block=256, one float4 chunk per thread, lane-contiguous
// LDG.128 per instruction, unroll-5 (cnt=20 -> 4 iterations, no tail),
// streaming cache hints, int32 indexing, launch_bounds(256,6).
// Measured 6.86 TB/s = LTS chip cap (path-independent per B300 microarch);
// restructures beyond this shape regressed (R4 pairing, R5 block=512).
// R10 trim: scope pair read as one LDG.64 (int2) instead of two LDG.32.

__global__ void __launch_bounds__(256, 6)
readout_mean_v4(const float4* __restrict__ A,
                const int2* __restrict__ scope,
                float4* __restrict__ out,
                int n_graphs, int chunks, int n_atoms)
{
    int total = n_graphs * chunks;                       // 3.75M, fits int32
    int t = blockIdx.x * blockDim.x + threadIdx.x;
    if (t >= total) return;

    int g = t / chunks;
    int c = t - g * chunks;

    int2 sp = __ldg(scope + g);                          // (start, size) in one LDG.64
    int start = sp.x;
    int size  = sp.y;

    // Branch-free clamp to [0, n_atoms)
    start = max(start, 0);
    int cnt = min(start + size, n_atoms) - start;
    cnt = max(cnt, 0);

    const float4* p = A + start * chunks + c;            // <= 75M elems, fits int32

    float4 acc = make_float4(0.f, 0.f, 0.f, 0.f);
    int i = 0;
    // 5 independent streaming LDG.128 per iteration; cnt=20 -> 4 iterations, no tail
    for (; i + 5 <= cnt; i += 5) {
        const float4* q = p + i * chunks;
        float4 v0 = __ldcs(q);
        float4 v1 = __ldcs(q + chunks);
        float4 v2 = __ldcs(q + 2 * chunks);
        float4 v3 = __ldcs(q + 3 * chunks);
        float4 v4 = __ldcs(q + 4 * chunks);
        acc.x += (v0.x + v1.x) + (v2.x + v3.x) + v4.x;
        acc.y += (v0.y + v1.y) + (v2.y + v3.y) + v4.y;
        acc.z += (v0.z + v1.z) + (v2.z + v3.z) + v4.z;
        acc.w += (v0.w + v1.w) + (v2.w + v3.w) + v4.w;
    }
    for (; i < cnt; ++i) {
        float4 v = __ldcs(p + i * chunks);
        acc.x += v.x; acc.y += v.y; acc.z += v.z; acc.w += v.w;
    }

    // Reference semantics: divide by max(size,1); size==0 -> zeros (acc already 0)
    float inv = (size > 0) ? (1.0f / (float)size) : 0.0f;
    acc.x *= inv; acc.y *= inv; acc.z *= inv; acc.w *= inv;

    __stcs(out + g * chunks + c, acc);
}

// Scalar fallback for D % 4 != 0
__global__ void readout_mean_scalar(const float* __restrict__ A,
                                    const int2* __restrict__ scope,
                                    float* __restrict__ out,
                                    int n_graphs, int D, int n_atoms)
{
    long long total = (long long)n_graphs * D;
    long long t = (long long)blockIdx.x * blockDim.x + threadIdx.x;
    if (t >= total) return;

    int g = (int)(t / D);
    int d = (int)(t - (long long)g * D);

    int2 sp = __ldg(scope + g);
    int start = sp.x;
    int size  = sp.y;

    start = max(start, 0);
    int cnt = min(start + size, n_atoms) - start;
    cnt = max(cnt, 0);

    const float* p = A + (long long)start * D + d;
    float acc = 0.f;
    for (int i = 0; i < cnt; ++i)
        acc += __ldcs(p + (long long)i * D);

    float inv = (size > 0) ? (1.0f / (float)size) : 0.0f;
    out[(long long)g * D + d] = acc * inv;
}

extern "C" void kernel_launch(void* const* d_in, const int* in_sizes, int n_in,
                              void* d_out, int out_size)
{
    const float* atom_hiddens = (const float*)d_in[0];
    const int2*  a_scope      = (const int2*)d_in[1];

    int n_graphs = in_sizes[1] / 2;
    int D = out_size / n_graphs;              // 300
    int n_atoms = (int)((long long)in_sizes[0] / D);

    if ((D & 3) == 0) {
        int chunks = D / 4;                   // 75
        long long total = (long long)n_graphs * chunks;
        int threads = 256;
        int blocks = (int)((total + threads - 1) / threads);
        readout_mean_v4<<<blocks, threads>>>(
            (const float4*)atom_hiddens, a_scope, (float4*)d_out,
            n_graphs, chunks, n_atoms);
    } else {
        long long total = (long long)n_graphs * D;
        int threads = 256;
        int blocks = (int)((total + threads - 1) / threads);
        readout_mean_scalar<<<blocks, threads>>>(
            atom_hiddens, a_scope, (float*)d_out, n_graphs, D, n_atoms);
    }
}

// round 12
// speedup vs baseline: 1.0028x; 1.0028x over previous
#include <cuda_runtime.h>
#include <cuda_bf16.h>
#include <cstdint>

// Segment-mean readout:
//   out[g, :] = mean(atom_hiddens[start_g : start_g+size_g, :])   (0 if size_g == 0)
// atom_hiddens: [N_ATOMS, D] float32       (1M x 300)
// a_scope:      [N_GRAPHS, 2] int32        (start, size)
//
// HBM/LTS-roofline streaming: 1.2 GB read + 60 MB write, zero reuse.
// CONVERGED: exact reproduction of the best-measured config (R3, 181.4us,
// DRAM=86.4%, 6.85 TB/s = chip LTS cap). block=256, one float4 chunk per
// thread (lane-contiguous LDG.128 per instruction), unroll-5 (cnt=20 -> 4
// iterations, no tail), __ldcs/__stcs streaming hints, int32 indexing,
// natural register allocation (44 regs, 5 blocks/SM).
// Measured-and-rejected variants: 2-chunk/thread pairing (204us, per-LDG
// stride broke sector utilization), block=512 (189us, occ quantization),
// launch_bounds(256,6) / int2 scope load (182.7-183.3us, neutral-to-worse).

__global__ void readout_mean_v4(const float4* __restrict__ A,
                                const int* __restrict__ scope,
                                float4* __restrict__ out,
                                int n_graphs, int chunks, int n_atoms)
{
    int total = n_graphs * chunks;                       // 3.75M, fits int32
    int t = blockIdx.x * blockDim.x + threadIdx.x;
    if (t >= total) return;

    int g = t / chunks;
    int c = t - g * chunks;

    int start = __ldg(scope + 2 * g);
    int size  = __ldg(scope + 2 * g + 1);

    // Defensive clamp to [0, n_atoms)
    if (start < 0) start = 0;
    int end = start + size;
    if (end > n_atoms) end = n_atoms;
    int cnt = end - start;
    if (cnt < 0) cnt = 0;

    const float4* p = A + start * chunks + c;            // <= 75M elems, fits int32

    float4 acc = make_float4(0.f, 0.f, 0.f, 0.f);
    int i = 0;
    // 5 independent streaming LDG.128 per iteration; cnt=20 -> 4 iterations, no tail
    for (; i + 5 <= cnt; i += 5) {
        const float4* q = p + i * chunks;
        float4 v0 = __ldcs(q);
        float4 v1 = __ldcs(q + chunks);
        float4 v2 = __ldcs(q + 2 * chunks);
        float4 v3 = __ldcs(q + 3 * chunks);
        float4 v4 = __ldcs(q + 4 * chunks);
        acc.x += (v0.x + v1.x) + (v2.x + v3.x) + v4.x;
        acc.y += (v0.y + v1.y) + (v2.y + v3.y) + v4.y;
        acc.z += (v0.z + v1.z) + (v2.z + v3.z) + v4.z;
        acc.w += (v0.w + v1.w) + (v2.w + v3.w) + v4.w;
    }
    for (; i < cnt; ++i) {
        float4 v = __ldcs(p + i * chunks);
        acc.x += v.x; acc.y += v.y; acc.z += v.z; acc.w += v.w;
    }

    // Reference semantics: divide by max(size,1); size==0 -> zeros (acc already 0)
    float inv = (size > 0) ? (1.0f / (float)size) : 0.0f;
    acc.x *= inv; acc.y *= inv; acc.z *= inv; acc.w *= inv;

    __stcs(out + g * chunks + c, acc);
}

// Scalar fallback for D % 4 != 0
__global__ void readout_mean_scalar(const float* __restrict__ A,
                                    const int* __restrict__ scope,
                                    float* __restrict__ out,
                                    int n_graphs, int D, int n_atoms)
{
    long long total = (long long)n_graphs * D;
    long long t = (long long)blockIdx.x * blockDim.x + threadIdx.x;
    if (t >= total) return;

    int g = (int)(t / D);
    int d = (int)(t - (long long)g * D);

    int start = scope[2 * g];
    int size  = scope[2 * g + 1];

    if (start < 0) start = 0;
    int end = start + size;
    if (end > n_atoms) end = n_atoms;
    int cnt = end - start;
    if (cnt < 0) cnt = 0;

    const float* p = A + (long long)start * D + d;
    float acc = 0.f;
    for (int i = 0; i < cnt; ++i)
        acc += __ldcs(p + (long long)i * D);

    float inv = (size > 0) ? (1.0f / (float)size) : 0.0f;
    out[(long long)g * D + d] = acc * inv;
}

extern "C" void kernel_launch(void* const* d_in, const int* in_sizes, int n_in,
                              void* d_out, int out_size)
{
    const float* atom_hiddens = (const float*)d_in[0];
    const int*   a_scope      = (const int*)d_in[1];

    int n_graphs = in_sizes[1] / 2;
    int D = out_size / n_graphs;              // 300
    int n_atoms = (int)((long long)in_sizes[0] / D);

    if ((D & 3) == 0) {
        int chunks = D / 4;                   // 75
        long long total = (long long)n_graphs * chunks;
        int threads = 256;
        int blocks = (int)((total + threads - 1) / threads);
        readout_mean_v4<<<blocks, threads>>>(
            (const float4*)atom_hiddens, a_scope, (float4*)d_out,
            n_graphs, chunks, n_atoms);
    } else {
        long long total = (long long)n_graphs * D;
        int threads = 256;
        int blocks = (int)((total + threads - 1) / threads);
        readout_mean_scalar<<<blocks, threads>>>(
            atom_hiddens, a_scope, (float*)d_out, n_graphs, D, n_atoms);
    }
}

// round 13
// speedup vs baseline: 1.0143x; 1.0115x over previous
#include <cuda_runtime.h>
#include <cuda_bf16.h>
#include <cstdint>

// Segment-mean readout:
//   out[g, :] = mean(atom_hiddens[start_g : start_g+size_g, :])   (0 if size_g == 0)
// atom_hiddens: [N_ATOMS, D] float32       (1M x 300)
// a_scope:      [N_GRAPHS, 2] int32        (start, size)
//
// HBM-roofline streaming: 1.2 GB read + 60 MB write, zero reuse.
// Converged shape (R3-class, 181-183us band, DRAM ~86%, ~6.8 TB/s):
// block=256, one float4 chunk per thread (lane-contiguous LDG.128 per
// instruction), unroll-5 (cnt=20 -> 4 iterations, no tail), __ldcs/__stcs,
// int32 indexing. R13: chunks specialized as compile-time constant (75) so
// the per-thread t/chunks division becomes mul-hi+shift (shorter prologue
// before first load issue).
// Measured-and-rejected: 2-chunk/thread pairing (204us), block=512 (189us),
// launch_bounds(256,6) and int2 scope load (neutral).

template <int CHUNKS>
__global__ void readout_mean_v4_c(const float4* __restrict__ A,
                                  const int* __restrict__ scope,
                                  float4* __restrict__ out,
                                  int n_graphs, int n_atoms)
{
    int total = n_graphs * CHUNKS;                       // 3.75M, fits int32
    int t = blockIdx.x * blockDim.x + threadIdx.x;
    if (t >= total) return;

    int g = t / CHUNKS;                                  // mul-hi + shift
    int c = t - g * CHUNKS;

    int start = __ldg(scope + 2 * g);
    int size  = __ldg(scope + 2 * g + 1);

    // Defensive clamp to [0, n_atoms)
    if (start < 0) start = 0;
    int end = start + size;
    if (end > n_atoms) end = n_atoms;
    int cnt = end - start;
    if (cnt < 0) cnt = 0;

    const float4* p = A + start * CHUNKS + c;            // <= 75M elems, fits int32

    float4 acc = make_float4(0.f, 0.f, 0.f, 0.f);
    int i = 0;
    // 5 independent streaming LDG.128 per iteration; cnt=20 -> 4 iterations, no tail
    for (; i + 5 <= cnt; i += 5) {
        const float4* q = p + i * CHUNKS;
        float4 v0 = __ldcs(q);
        float4 v1 = __ldcs(q + CHUNKS);
        float4 v2 = __ldcs(q + 2 * CHUNKS);
        float4 v3 = __ldcs(q + 3 * CHUNKS);
        float4 v4 = __ldcs(q + 4 * CHUNKS);
        acc.x += (v0.x + v1.x) + (v2.x + v3.x) + v4.x;
        acc.y += (v0.y + v1.y) + (v2.y + v3.y) + v4.y;
        acc.z += (v0.z + v1.z) + (v2.z + v3.z) + v4.z;
        acc.w += (v0.w + v1.w) + (v2.w + v3.w) + v4.w;
    }
    for (; i < cnt; ++i) {
        float4 v = __ldcs(p + i * CHUNKS);
        acc.x += v.x; acc.y += v.y; acc.z += v.z; acc.w += v.w;
    }

    // Reference semantics: divide by max(size,1); size==0 -> zeros (acc already 0)
    float inv = (size > 0) ? (1.0f / (float)size) : 0.0f;
    acc.x *= inv; acc.y *= inv; acc.z *= inv; acc.w *= inv;

    __stcs(out + g * CHUNKS + c, acc);
}

// Generic runtime-chunks version (fallback for D%4==0 but D!=300)
__global__ void readout_mean_v4(const float4* __restrict__ A,
                                const int* __restrict__ scope,
                                float4* __restrict__ out,
                                int n_graphs, int chunks, int n_atoms)
{
    int total = n_graphs * chunks;
    int t = blockIdx.x * blockDim.x + threadIdx.x;
    if (t >= total) return;

    int g = t / chunks;
    int c = t - g * chunks;

    int start = __ldg(scope + 2 * g);
    int size  = __ldg(scope + 2 * g + 1);

    if (start < 0) start = 0;
    int end = start + size;
    if (end > n_atoms) end = n_atoms;
    int cnt = end - start;
    if (cnt < 0) cnt = 0;

    const float4* p = A + start * chunks + c;

    float4 acc = make_float4(0.f, 0.f, 0.f, 0.f);
    int i = 0;
    for (; i + 5 <= cnt; i += 5) {
        const float4* q = p + i * chunks;
        float4 v0 = __ldcs(q);
        float4 v1 = __ldcs(q + chunks);
        float4 v2 = __ldcs(q + 2 * chunks);
        float4 v3 = __ldcs(q + 3 * chunks);
        float4 v4 = __ldcs(q + 4 * chunks);
        acc.x += (v0.x + v1.x) + (v2.x + v3.x) + v4.x;
        acc.y += (v0.y + v1.y) + (v2.y + v3.y) + v4.y;
        acc.z += (v0.z + v1.z) + (v2.z + v3.z) + v4.z;
        acc.w += (v0.w + v1.w) + (v2.w + v3.w) + v4.w;
    }
    for (; i < cnt; ++i) {
        float4 v = __ldcs(p + i * chunks);
        acc.x += v.x; acc.y += v.y; acc.z += v.z; acc.w += v.w;
    }

    float inv = (size > 0) ? (1.0f / (float)size) : 0.0f;
    acc.x *= inv; acc.y *= inv; acc.z *= inv; acc.w *= inv;

    __stcs(out + g * chunks + c, acc);
}

// Scalar fallback for D % 4 != 0
__global__ void readout_mean_scalar(const float* __restrict__ A,
                                    const int* __restrict__ scope,
                                    float* __restrict__ out,
                                    int n_graphs, int D, int n_atoms)
{
    long long total = (long long)n_graphs * D;
    long long t = (long long)blockIdx.x * blockDim.x + threadIdx.x;
    if (t >= total) return;

    int g = (int)(t / D);
    int d = (int)(t - (long long)g * D);

    int start = scope[2 * g];
    int size  = scope[2 * g + 1];

    if (start < 0) start = 0;
    int end = start + size;
    if (end > n_atoms) end = n_atoms;
    int cnt = end - start;
    if (cnt < 0) cnt = 0;

    const float* p = A + (long long)start * D + d;
    float acc = 0.f;
    for (int i = 0; i < cnt; ++i)
        acc += __ldcs(p + (long long)i * D);

    float inv = (size > 0) ? (1.0f / (float)size) : 0.0f;
    out[(long long)g * D + d] = acc * inv;
}

extern "C" void kernel_launch(void* const* d_in, const int* in_sizes, int n_in,
                              void* d_out, int out_size)
{
    const float* atom_hiddens = (const float*)d_in[0];
    const int*   a_scope      = (const int*)d_in[1];

    int n_graphs = in_sizes[1] / 2;
    int D = out_size / n_graphs;              // 300
    int n_atoms = (int)((long long)in_sizes[0] / D);

    if (D == 300) {
        constexpr int CH = 75;
        long long total = (long long)n_graphs * CH;
        int threads = 256;
        int blocks = (int)((total + threads - 1) / threads);
        readout_mean_v4_c<CH><<<blocks, threads>>>(
            (const float4*)atom_hiddens, a_scope, (float4*)d_out,
            n_graphs, n_atoms);
    } else if ((D & 3) == 0) {
        int chunks = D / 4;
        long long total = (long long)n_graphs * chunks;
        int threads = 256;
        int blocks = (int)((total + threads - 1) / threads);
        readout_mean_v4<<<blocks, threads>>>(
            (const float4*)atom_hiddens, a_scope, (float4*)d_out,
            n_graphs, chunks, n_atoms);
    } else {
        long long total = (long long)n_graphs * D;
        int threads = 256;
        int blocks = (int)((total + threads - 1) / threads);
        readout_mean_scalar<<<blocks, threads>>>(
            atom_hiddens, a_scope, (float*)d_out, n_graphs, D, n_atoms);
    }
}